// round 16
// baseline (speedup 1.0000x reference)
#include <cuda_runtime.h>
#include <math.h>
#include <stdint.h>

#define B_ 8
#define S_ 1024
#define H_ 1024
#define D_ 512
#define N_ 16
#define BS_ (B_*S_)
#define DECAYF 0.9f
#define EPS_LN 1e-5f

__device__ float g_items  [BS_*D_];
__device__ float g_queries[BS_*H_];
__device__ float g_khid   [BS_*H_];
__device__ float g_keys   [BS_*D_];
__device__ float g_bound  [BS_*D_];
__device__ float g_v      [BS_*D_];
__device__ float g_preg1  [BS_*H_];
__device__ float g_preo   [BS_*H_];
__device__ float g_mixed  [BS_*D_];
__device__ float g_ctx    [BS_*D_];

__device__ __forceinline__ float gelu_f(float x) {
    return 0.5f * x * (1.0f + erff(x * 0.70710678118654752f));
}
__device__ __forceinline__ void tfsplit(float f, uint32_t& hi, uint32_t& lo) {
    hi = __float_as_uint(f) & 0xFFFFE000u;
    lo = __float_as_uint(f - __uint_as_float(hi));
}
__device__ __forceinline__ void mma_tf32(float* c, const uint32_t* a, const uint32_t* b) {
    asm volatile(
        "mma.sync.aligned.m16n8k8.row.col.f32.tf32.tf32.f32 "
        "{%0,%1,%2,%3}, {%4,%5,%6,%7}, {%8,%9}, {%0,%1,%2,%3};\n"
        : "+f"(c[0]), "+f"(c[1]), "+f"(c[2]), "+f"(c[3])
        : "r"(a[0]), "r"(a[1]), "r"(a[2]), "r"(a[3]), "r"(b[0]), "r"(b[1]));
}
__device__ __forceinline__ uint32_t smem_u32(const void* p) {
    return (uint32_t)__cvta_generic_to_shared(p);
}
#define CP_ASYNC16(dst, src) \
    asm volatile("cp.async.cg.shared.global [%0], [%1], 16;\n" :: "r"(dst), "l"(src))
#define CP_COMMIT asm volatile("cp.async.commit_group;\n")
#define CP_WAIT0  asm volatile("cp.async.wait_group 0;\n" ::: "memory")

// ---- 3xTF32 GEMM, cp.async double-buffered, masked split, occ-2, optional dual-A ----
__global__ __launch_bounds__(256, 2)
void tgemm_kernel(const float* __restrict__ A, int K1,
                  const float* __restrict__ A2, int K2,
                  const float* __restrict__ W,
                  const float* __restrict__ bias, float* __restrict__ C,
                  int M, int N, int act, int accum)
{
    __shared__ float As[2][128][20];
    __shared__ float Bs[2][16][136];
    int tid = threadIdx.x;
    int lane = tid & 31, wid = tid >> 5;
    int wm = wid & 1, wn = wid >> 1;
    int gid = lane >> 2, tg = lane & 3;
    int row0 = blockIdx.y * 128, col0 = blockIdx.x * 128;

    float acc[4][4][4];
#pragma unroll
    for (int mi = 0; mi < 4; mi++)
#pragma unroll
        for (int ni = 0; ni < 4; ni++)
#pragma unroll
            for (int f = 0; f < 4; f++) acc[mi][ni][f] = 0.f;

    auto copy_tile = [&](int kt, int s) {
        int kcol = kt * 16;
#pragma unroll
        for (int q = 0; q < 2; q++) {
            int id = tid * 2 + q;
            int ar = id >> 2, seg = id & 3;
            const float* srcA = (kcol < K1)
                ? A  + (size_t)(row0 + ar) * K1 + kcol + seg * 4
                : A2 + (size_t)(row0 + ar) * K2 + (kcol - K1) + seg * 4;
            CP_ASYNC16(smem_u32(&As[s][ar][seg * 4]), srcA);
            int kr = id >> 5, bc = (id & 31) * 4;
            CP_ASYNC16(smem_u32(&Bs[s][kr][bc]),
                       W + (size_t)(kcol + kr) * N + col0 + bc);
        }
        CP_COMMIT;
    };

    int nk = (K1 + K2) >> 4;
    copy_tile(0, 0);
    for (int it = 0; it < nk; ++it) {
        CP_WAIT0;
        __syncthreads();
        if (it + 1 < nk) copy_tile(it + 1, (it + 1) & 1);
        int p = it & 1;
#pragma unroll
        for (int kk = 0; kk < 16; kk += 8) {
            uint32_t bH[4][2], bL[4][2];
#pragma unroll
            for (int ni = 0; ni < 4; ni++) {
                int n0 = wn * 32 + ni * 8 + gid;
                tfsplit(Bs[p][kk + tg][n0],     bH[ni][0], bL[ni][0]);
                tfsplit(Bs[p][kk + tg + 4][n0], bH[ni][1], bL[ni][1]);
            }
#pragma unroll
            for (int mi = 0; mi < 4; mi++) {
                int r0 = wm * 64 + mi * 16 + gid;
                uint32_t aH[4], aL[4];
                tfsplit(As[p][r0][kk + tg],         aH[0], aL[0]);
                tfsplit(As[p][r0 + 8][kk + tg],     aH[1], aL[1]);
                tfsplit(As[p][r0][kk + tg + 4],     aH[2], aL[2]);
                tfsplit(As[p][r0 + 8][kk + tg + 4], aH[3], aL[3]);
#pragma unroll
                for (int ni = 0; ni < 4; ni++) {
                    mma_tf32(acc[mi][ni], aH, bL[ni]);
                    mma_tf32(acc[mi][ni], aL, bH[ni]);
                    mma_tf32(acc[mi][ni], aH, bH[ni]);
                }
            }
        }
    }
#pragma unroll
    for (int mi = 0; mi < 4; mi++)
#pragma unroll
        for (int ni = 0; ni < 4; ni++) {
            int r = row0 + wm * 64 + mi * 16 + gid;
            int c = col0 + wn * 32 + ni * 8 + tg * 2;
#pragma unroll
            for (int h = 0; h < 2; h++) {
                int rr = r + h * 8;
                float o0 = acc[mi][ni][h * 2 + 0];
                float o1 = acc[mi][ni][h * 2 + 1];
                if (bias) { o0 += bias[c]; o1 += bias[c + 1]; }
                float* cp = C + (size_t)rr * N + c;
                if (accum) { o0 += cp[0]; o1 += cp[1]; }
                if (act == 1) { o0 = gelu_f(o0); o1 = gelu_f(o1); }
                *(float2*)cp = make_float2(o0, o1);
            }
        }
}

// register sliding-window circular conv (sign=1) / corr (sign=0); 4 rows/block
// bmode: 0 = B shared; 1 = B row = gr&1023; 2 = B row = gr
__global__ __launch_bounds__(256)
void circ2_kernel(const float* __restrict__ A, const float* __restrict__ Bsrc,
                  float* __restrict__ out, int bmode, int sign)
{
    __shared__ float ad[4][1024];
    __shared__ float bvs[4][512];
    int tid = threadIdx.x;
    int lr = tid >> 6, lt = tid & 63;
    int gr = blockIdx.x * 4 + lr;
    const float* Arow = A + (size_t)gr * 512;
    const float* Brow = (bmode == 0) ? Bsrc
                      : (bmode == 1) ? (Bsrc + (size_t)(gr & 1023) * 512)
                                     : (Bsrc + (size_t)gr * 512);
    for (int i = lt; i < 1024; i += 64) ad[lr][i] = Arow[i & 511];
    for (int i = lt; i < 512; i += 64)  bvs[lr][i] = Brow[i];
    __syncthreads();

    int d0 = lt * 8;
    float accv[8];
#pragma unroll
    for (int i = 0; i < 8; i++) accv[i] = 0.f;
    float win[16];
    const float* adr = ad[lr];
    const float* bvr = bvs[lr];

    if (sign) {
        int base = 512 + d0 - 8;
        float4 p0 = *(const float4*)(adr + base + 8);
        float4 p1 = *(const float4*)(adr + base + 12);
        win[8] = p0.x; win[9] = p0.y; win[10] = p0.z; win[11] = p0.w;
        win[12] = p1.x; win[13] = p1.y; win[14] = p1.z; win[15] = p1.w;
        for (int m0 = 0; m0 < 512; m0 += 8) {
            float4 w0 = *(const float4*)(adr + base);
            float4 w1 = *(const float4*)(adr + base + 4);
            win[0] = w0.x; win[1] = w0.y; win[2] = w0.z; win[3] = w0.w;
            win[4] = w1.x; win[5] = w1.y; win[6] = w1.z; win[7] = w1.w;
            float4 b0 = *(const float4*)(bvr + m0);
            float4 b1 = *(const float4*)(bvr + m0 + 4);
            float bb[8] = {b0.x, b0.y, b0.z, b0.w, b1.x, b1.y, b1.z, b1.w};
#pragma unroll
            for (int mm = 0; mm < 8; mm++)
#pragma unroll
                for (int i = 0; i < 8; i++)
                    accv[i] += bb[mm] * win[8 + i - mm];
#pragma unroll
            for (int k = 0; k < 8; k++) win[8 + k] = win[k];
            base -= 8;
        }
    } else {
        int base = 512 - d0 - 8;
        float4 p0 = *(const float4*)(adr + base);
        float4 p1 = *(const float4*)(adr + base + 4);
        win[0] = p0.x; win[1] = p0.y; win[2] = p0.z; win[3] = p0.w;
        win[4] = p1.x; win[5] = p1.y; win[6] = p1.z; win[7] = p1.w;
        for (int m0 = 0; m0 < 512; m0 += 8) {
            float4 w0 = *(const float4*)(adr + base + 8);
            float4 w1 = *(const float4*)(adr + base + 12);
            win[8] = w0.x; win[9] = w0.y; win[10] = w0.z; win[11] = w0.w;
            win[12] = w1.x; win[13] = w1.y; win[14] = w1.z; win[15] = w1.w;
            float4 b0 = *(const float4*)(bvr + m0);
            float4 b1 = *(const float4*)(bvr + m0 + 4);
            float bb[8] = {b0.x, b0.y, b0.z, b0.w, b1.x, b1.y, b1.z, b1.w};
#pragma unroll
            for (int mm = 0; mm < 8; mm++)
#pragma unroll
                for (int i = 0; i < 8; i++)
                    accv[i] += bb[mm] * win[8 + mm - i];
#pragma unroll
            for (int k = 0; k < 8; k++) win[k] = win[k + 8];
            base += 8;
        }
    }
    *(float4*)(out + (size_t)gr * 512 + d0) = make_float4(accv[0], accv[1], accv[2], accv[3]);
    *(float4*)(out + (size_t)gr * 512 + d0 + 4) = make_float4(accv[4], accv[5], accv[6], accv[7]);
}

__global__ __launch_bounds__(128)
void rownorm_kernel(float* __restrict__ keys)
{
    int row = blockIdx.x, tid = threadIdx.x;
    __shared__ float rs[4];
    float4 v = *(float4*)(keys + (size_t)row * 512 + tid * 4);
    float ss = v.x*v.x + v.y*v.y + v.z*v.z + v.w*v.w;
#pragma unroll
    for (int off = 16; off; off >>= 1) ss += __shfl_xor_sync(0xffffffffu, ss, off);
    int w = tid >> 5, l = tid & 31;
    if (l == 0) rs[w] = ss;
    __syncthreads();
    ss = rs[0] + rs[1] + rs[2] + rs[3];
    float inv = 1.f / fmaxf(sqrtf(ss), 1e-12f);
    v.x *= inv; v.y *= inv; v.z *= inv; v.w *= inv;
    *(float4*)(keys + (size_t)row * 512 + tid * 4) = v;
}

// ---- phase 2 FUSED (1024 threads): blocks 0-7 scan (32 warps, 4 barriers/step);
//      blocks 8..519 Wo gemm tiles (4x8 warp grid, 32x16 warp tile) ----
__global__ __launch_bounds__(1024, 1)
void phase2_fused(const float* __restrict__ v_g, const float* __restrict__ bound_g,
                  const float* __restrict__ preg1_g, const float* __restrict__ Wg1,
                  const float* __restrict__ Wg2, const float* __restrict__ bg2,
                  const float* __restrict__ bsa, float* __restrict__ mixed_g,
                  float* __restrict__ hcm_out,
                  const float* __restrict__ Qm, const float* __restrict__ Wo,
                  const float* __restrict__ bo, float* __restrict__ preo)
{
    __shared__ __align__(16) char sbuf[45312];
    int tid = threadIdx.x;
    int lane = tid & 31, wid = tid >> 5;

    if (blockIdx.x >= 8) {
        // ---- GEMM path: one 128x128 tile of preo = Qm @ Wo + bo ----
        float (*As)[128][20] = (float (*)[128][20])sbuf;
        float (*Bs)[16][136] = (float (*)[16][136])(sbuf + 20480);
        int t = blockIdx.x - 8;
        int col0 = (t & 7) * 128, row0 = (t >> 3) * 128;
        int wm = wid & 3, wn = wid >> 2;       // 4x8 warp grid, warp tile 32x16
        int gid = lane >> 2, tg = lane & 3;
        const int K = H_, Nn = H_;

        float acc[2][2][4];
#pragma unroll
        for (int mi = 0; mi < 2; mi++)
#pragma unroll
            for (int ni = 0; ni < 2; ni++)
#pragma unroll
                for (int f = 0; f < 4; f++) acc[mi][ni][f] = 0.f;

        auto copy_tile = [&](int kt, int s) {
            if (tid < 512) {
                int ar = tid >> 2, seg = tid & 3;
                CP_ASYNC16(smem_u32(&As[s][ar][seg * 4]),
                           Qm + (size_t)(row0 + ar) * K + kt * 16 + seg * 4);
            } else {
                int id = tid - 512;
                int kr = id >> 5, bc = (id & 31) * 4;
                CP_ASYNC16(smem_u32(&Bs[s][kr][bc]),
                           Wo + (size_t)(kt * 16 + kr) * Nn + col0 + bc);
            }
            CP_COMMIT;
        };

        int nk = K >> 4;
        copy_tile(0, 0);
        for (int it = 0; it < nk; ++it) {
            CP_WAIT0;
            __syncthreads();
            if (it + 1 < nk) copy_tile(it + 1, (it + 1) & 1);
            int p = it & 1;
#pragma unroll
            for (int kk = 0; kk < 16; kk += 8) {
                uint32_t bH[2][2], bL[2][2];
#pragma unroll
                for (int ni = 0; ni < 2; ni++) {
                    int n0 = wn * 16 + ni * 8 + gid;
                    tfsplit(Bs[p][kk + tg][n0],     bH[ni][0], bL[ni][0]);
                    tfsplit(Bs[p][kk + tg + 4][n0], bH[ni][1], bL[ni][1]);
                }
#pragma unroll
                for (int mi = 0; mi < 2; mi++) {
                    int r0 = wm * 32 + mi * 16 + gid;
                    uint32_t aH[4], aL[4];
                    tfsplit(As[p][r0][kk + tg],         aH[0], aL[0]);
                    tfsplit(As[p][r0 + 8][kk + tg],     aH[1], aL[1]);
                    tfsplit(As[p][r0][kk + tg + 4],     aH[2], aL[2]);
                    tfsplit(As[p][r0 + 8][kk + tg + 4], aH[3], aL[3]);
#pragma unroll
                    for (int ni = 0; ni < 2; ni++) {
                        mma_tf32(acc[mi][ni], aH, bL[ni]);
                        mma_tf32(acc[mi][ni], aL, bH[ni]);
                        mma_tf32(acc[mi][ni], aH, bH[ni]);
                    }
                }
            }
        }
#pragma unroll
        for (int mi = 0; mi < 2; mi++)
#pragma unroll
            for (int ni = 0; ni < 2; ni++) {
                int r = row0 + wm * 32 + mi * 16 + gid;
                int c = col0 + wn * 16 + ni * 8 + tg * 2;
#pragma unroll
                for (int h = 0; h < 2; h++) {
                    int rr = r + h * 8;
                    float o0 = acc[mi][ni][h * 2 + 0] + bo[c];
                    float o1 = acc[mi][ni][h * 2 + 1] + bo[c + 1];
                    *(float2*)(preo + (size_t)rr * Nn + c) = make_float2(o0, o1);
                }
            }
        return;
    }

    // ---------- scan path: 32 warps ----------
    float* hcm_s   = (float*)sbuf;                 // 8192
    float* g_s     = hcm_s + 8192;                 // 1024
    float* v_s     = g_s + 1024;                   // 2*512
    float* bnd_s   = v_s + 1024;                   // 2*512
    float* scores_s= bnd_s + 1024;                 // 16
    float* stats_s = scores_s + 16;                // 16
    float* gpart   = stats_s + 16;                 // 32

    int b = blockIdx.x;
    int w = wid, l = lane;
    int slot = w & 15;
    int ubase = (w >> 4) * 512;                    // gate-partial unit base

    float wg1[16], wg2r[16], hr[16];
#pragma unroll
    for (int n = 0; n < 16; ++n) {
        wg1[n] = Wg1[(size_t)(1536 + n) * 1024 + tid];
        wg2r[n] = Wg2[(size_t)(ubase + l + 32 * n) * 16 + slot];
        hr[n] = 0.f;
    }
    float bg2w = bg2[slot];
    float bsa0 = bsa[0];

    for (int i = tid; i < 8192; i += 1024) hcm_s[i] = 0.f;

    size_t rbase = (size_t)b * S_;
    // staging owned by warps 16-31 (d2 = tid-512)
    float Av2 = 0.f, Ab2 = 0.f, Bv2 = 0.f, Bb2 = 0.f;
    if (tid >= 512) {
        int d2 = tid - 512;
        v_s[d2]   = v_g[rbase * 512 + d2];
        bnd_s[d2] = bound_g[rbase * 512 + d2];
        Av2 = v_g[(rbase + 1) * 512 + d2];
        Ab2 = bound_g[(rbase + 1) * 512 + d2];
        Bv2 = v_g[(rbase + 2) * 512 + d2];
        Bb2 = bound_g[(rbase + 2) * 512 + d2];
    }
    float pg = preg1_g[rbase * 1024 + tid];
    float Ap = preg1_g[(rbase + 1) * 1024 + tid];
    float Bp = preg1_g[(rbase + 2) * 1024 + tid];
    __syncthreads();

    for (int t = 0; t < S_; ++t) {
        int cur = t & 1;
        // segA: scores+stats (warps 0-15, register hcm)
        if (w < 16) {
            float dv = 0.f, dh = 0.f;
#pragma unroll
            for (int i = 0; i < 16; ++i) {
                dv += hr[i] * v_s[cur * 512 + l + i * 32];
                dh += hr[i] * hr[i];
            }
#pragma unroll
            for (int off = 16; off; off >>= 1) {
                dv += __shfl_xor_sync(0xffffffffu, dv, off);
                dh += __shfl_xor_sync(0xffffffffu, dh, off);
            }
            if (l == 0) { scores_s[w] = dv + bsa0; stats_s[w] = sqrtf(dh); }
        }
        __syncthreads();                              // B1
        // segB: gating hidden (all 1024 units), staging (warps 16-31)
        float scr = (l < 16) ? scores_s[l] : -3.4e38f;
        {
            float a = pg;
#pragma unroll
            for (int n = 0; n < 16; ++n) a += stats_s[n] * wg1[n];
            g_s[tid] = gelu_f(a);
        }
        if (tid >= 512) {
            int d2 = tid - 512;
            v_s[(cur ^ 1) * 512 + d2] = Av2;
            bnd_s[(cur ^ 1) * 512 + d2] = Ab2;
            Av2 = Bv2; Ab2 = Bb2;
            if (t + 3 < S_) {
                size_t rb = rbase + t + 3;
                Bv2 = v_g[rb * 512 + d2];
                Bb2 = bound_g[rb * 512 + d2];
            }
        }
        pg = Ap; Ap = Bp;
        if (t + 3 < S_) Bp = preg1_g[(rbase + t + 3) * 1024 + tid];
        __syncthreads();                              // B2
        // segC1: gate partials (all 32 warps; 2 warps per slot)
        {
            float gp = 0.f;
#pragma unroll
            for (int i = 0; i < 16; ++i)
                gp += g_s[ubase + l + 32 * i] * wg2r[i];
#pragma unroll
            for (int off = 16; off; off >>= 1)
                gp += __shfl_xor_sync(0xffffffffu, gp, off);
            if (l == 0) gpart[w] = gp;
        }
        __syncthreads();                              // B3
        // segC2a: gw + softmax + mixed (warps 0-15; mixed reads live mirror)
        float gw = 0.f;
        if (w < 16) {
            gw = 1.f / (1.f + __expf(-(gpart[w] + gpart[w + 16] + bg2w)));
            float mxv = scr;
#pragma unroll
            for (int off = 8; off; off >>= 1)
                mxv = fmaxf(mxv, __shfl_xor_sync(0xffffffffu, mxv, off));
            float e = (l < 16) ? __expf(scr - mxv) : 0.f;
            float su = e;
#pragma unroll
            for (int off = 8; off; off >>= 1)
                su += __shfl_xor_sync(0xffffffffu, su, off);
            float myw = e / su;
            float mx = 0.f;
#pragma unroll
            for (int n = 0; n < 16; ++n)
                mx += __shfl_sync(0xffffffffu, myw, n) * hcm_s[n * 512 + tid];
            mixed_g[(rbase + t) * 512 + tid] = mx;
        }
        __syncthreads();                              // B4
        // segC2b: update own slot (warps 0-15)
        if (w < 16) {
#pragma unroll
            for (int i = 0; i < 16; ++i) {
                int d = l + 32 * i;
                hr[i] = DECAYF * hr[i] + gw * bnd_s[cur * 512 + d];
                hcm_s[w * 512 + d] = hr[i];
            }
        }
    }
    __syncthreads();
    for (int i = tid; i < 8192; i += 1024)
        hcm_out[(size_t)b * 8192 + i] = hcm_s[i];
}

__global__ __launch_bounds__(256)
void ln_kernel(const float* __restrict__ hs, const float* __restrict__ preo,
               const float* __restrict__ lng, const float* __restrict__ lnb,
               float* __restrict__ out)
{
    int row = blockIdx.x, tid = threadIdx.x;
    __shared__ float rs[8], rs2[8];
    size_t base = (size_t)row * 1024;
    float v[4]; float s = 0.f, s2 = 0.f;
#pragma unroll
    for (int i = 0; i < 4; i++) {
        int h = tid + i * 256;
        float x = hs[base + h] + preo[base + h];
        v[i] = x; s += x; s2 += x * x;
    }
#pragma unroll
    for (int off = 16; off; off >>= 1) {
        s  += __shfl_xor_sync(0xffffffffu, s, off);
        s2 += __shfl_xor_sync(0xffffffffu, s2, off);
    }
    int w = tid >> 5, l = tid & 31;
    if (l == 0) { rs[w] = s; rs2[w] = s2; }
    __syncthreads();
    s = 0.f; s2 = 0.f;
#pragma unroll
    for (int i = 0; i < 8; i++) { s += rs[i]; s2 += rs2[i]; }
    float mu = s * (1.f / 1024.f);
    float var = s2 * (1.f / 1024.f) - mu * mu;
    float rstd = rsqrtf(var + EPS_LN);
#pragma unroll
    for (int i = 0; i < 4; i++) {
        int h = tid + i * 256;
        out[base + h] = (v[i] - mu) * rstd * lng[h] + lnb[h];
    }
}

extern "C" void kernel_launch(void* const* d_in, const int* in_sizes, int n_in,
                              void* d_out, int out_size)
{
    const float* hs  = (const float*)d_in[0];
    const float* pos = (const float*)d_in[1];
    const float* Wi  = (const float*)d_in[2];
    const float* bi  = (const float*)d_in[3];
    const float* Wq  = (const float*)d_in[4];
    const float* bq  = (const float*)d_in[5];
    const float* Wk1 = (const float*)d_in[6];
    const float* bk1 = (const float*)d_in[7];
    const float* Wk2 = (const float*)d_in[8];
    const float* bk2 = (const float*)d_in[9];
    const float* Wsa = (const float*)d_in[10];
    const float* bsa = (const float*)d_in[11];
    const float* Wg1 = (const float*)d_in[12];
    const float* bg1 = (const float*)d_in[13];
    const float* Wg2 = (const float*)d_in[14];
    const float* bg2 = (const float*)d_in[15];
    const float* Wo  = (const float*)d_in[16];
    const float* bo  = (const float*)d_in[17];
    const float* lng = (const float*)d_in[18];
    const float* lnb = (const float*)d_in[19];
    float* out = (float*)d_out;

    float *items, *queries, *khid, *keys, *bound, *v, *preg1, *preo, *mixed, *ctx;
    cudaGetSymbolAddress((void**)&items,   g_items);
    cudaGetSymbolAddress((void**)&queries, g_queries);
    cudaGetSymbolAddress((void**)&khid,    g_khid);
    cudaGetSymbolAddress((void**)&keys,    g_keys);
    cudaGetSymbolAddress((void**)&bound,   g_bound);
    cudaGetSymbolAddress((void**)&v,       g_v);
    cudaGetSymbolAddress((void**)&preg1,   g_preg1);
    cudaGetSymbolAddress((void**)&preo,    g_preo);
    cudaGetSymbolAddress((void**)&mixed,   g_mixed);
    cudaGetSymbolAddress((void**)&ctx,     g_ctx);

    dim3 gN(H_ / 128, BS_ / 128);
    dim3 gD(D_ / 128, BS_ / 128);

    tgemm_kernel<<<gN, 256>>>(hs, H_, nullptr, 0, Wq, bq, queries, BS_, H_, 0, 0);
    tgemm_kernel<<<gD, 256>>>(hs, H_, nullptr, 0, Wi, bi, items,   BS_, D_, 0, 0);
    tgemm_kernel<<<gN, 256>>>(queries, H_, nullptr, 0, Wk1, bk1, khid, BS_, H_, 1, 0);
    tgemm_kernel<<<gD, 256>>>(khid, H_, nullptr, 0, Wk2, bk2, keys, BS_, D_, 0, 0);
    rownorm_kernel<<<BS_, 128>>>(keys);
    circ2_kernel<<<BS_ / 4, 256>>>(keys, Wsa, v, 0, 1);      // v = conv(keys, Wsa)
    circ2_kernel<<<BS_ / 4, 256>>>(items, pos, bound, 1, 1); // bound = conv(items, pos)
    // fused: preg1 = [queries|items] @ Wg1[0:1536] + bg1
    tgemm_kernel<<<gN, 256>>>(queries, H_, items, D_, Wg1, bg1, preg1, BS_, H_, 0, 0);

    phase2_fused<<<8 + 512, 1024>>>(v, bound, preg1, Wg1, Wg2, bg2, bsa,
                                    mixed, out + (size_t)BS_ * H_,
                                    queries, Wo, bo, preo);

    circ2_kernel<<<BS_ / 4, 256>>>(keys, mixed, ctx, 2, 0);  // ctx = corr(mixed, keys)
    tgemm_kernel<<<gN, 256>>>(ctx, D_, nullptr, 0, Wo + (size_t)H_ * H_, nullptr, preo,
                              BS_, H_, 0, 1);
    ln_kernel<<<BS_, 256>>>(hs, preo, lng, lnb, out);
}

// round 17
// speedup vs baseline: 1.2567x; 1.2567x over previous
#include <cuda_runtime.h>
#include <math.h>
#include <stdint.h>

#define B_ 8
#define S_ 1024
#define H_ 1024
#define D_ 512
#define N_ 16
#define BS_ (B_*S_)
#define DECAYF 0.9f
#define EPS_LN 1e-5f

__device__ float g_items  [BS_*D_];
__device__ float g_queries[BS_*H_];
__device__ float g_khid   [BS_*H_];
__device__ float g_keys   [BS_*D_];
__device__ float g_bound  [BS_*D_];
__device__ float g_v      [BS_*D_];
__device__ float g_preg1  [BS_*H_];
__device__ float g_preo   [BS_*H_];
__device__ float g_mixed  [BS_*D_];
__device__ float g_ctx    [BS_*D_];

__device__ __forceinline__ float gelu_f(float x) {
    return 0.5f * x * (1.0f + erff(x * 0.70710678118654752f));
}
__device__ __forceinline__ void tfsplit(float f, uint32_t& hi, uint32_t& lo) {
    hi = __float_as_uint(f) & 0xFFFFE000u;
    lo = __float_as_uint(f - __uint_as_float(hi));
}
__device__ __forceinline__ void mma_tf32(float* c, const uint32_t* a, const uint32_t* b) {
    asm volatile(
        "mma.sync.aligned.m16n8k8.row.col.f32.tf32.tf32.f32 "
        "{%0,%1,%2,%3}, {%4,%5,%6,%7}, {%8,%9}, {%0,%1,%2,%3};\n"
        : "+f"(c[0]), "+f"(c[1]), "+f"(c[2]), "+f"(c[3])
        : "r"(a[0]), "r"(a[1]), "r"(a[2]), "r"(a[3]), "r"(b[0]), "r"(b[1]));
}
__device__ __forceinline__ uint32_t smem_u32(const void* p) {
    return (uint32_t)__cvta_generic_to_shared(p);
}
#define CP_ASYNC16(dst, src) \
    asm volatile("cp.async.cg.shared.global [%0], [%1], 16;\n" :: "r"(dst), "l"(src))
#define CP_COMMIT asm volatile("cp.async.commit_group;\n")
#define CP_WAIT0  asm volatile("cp.async.wait_group 0;\n" ::: "memory")

// ---- 3xTF32 GEMM, cp.async double-buffered, masked split, occ-2.
//      Optional dual-A (concatenated K) and dual-W (concatenated N, split outputs). ----
__global__ __launch_bounds__(256, 2)
void tgemm_kernel(const float* __restrict__ A, int K1,
                  const float* __restrict__ A2, int K2,
                  const float* __restrict__ W,  int N1,
                  const float* __restrict__ W2, int N2,
                  const float* __restrict__ bias, const float* __restrict__ bias2,
                  float* __restrict__ C, float* __restrict__ C2,
                  int act, int accum)
{
    __shared__ float As[2][128][20];
    __shared__ float Bs[2][16][136];
    int tid = threadIdx.x;
    int lane = tid & 31, wid = tid >> 5;
    int wm = wid & 1, wn = wid >> 1;
    int gid = lane >> 2, tg = lane & 3;
    int row0 = blockIdx.y * 128;

    // per-tile output selection (uniform per block)
    int cg = blockIdx.x * 128;
    const float* Wl; const float* biasl; float* Cl; int Nl; int col0;
    if (cg < N1) { Wl = W;  biasl = bias;  Cl = C;  Nl = N1; col0 = cg; }
    else         { Wl = W2; biasl = bias2; Cl = C2; Nl = N2; col0 = cg - N1; }

    float acc[4][4][4];
#pragma unroll
    for (int mi = 0; mi < 4; mi++)
#pragma unroll
        for (int ni = 0; ni < 4; ni++)
#pragma unroll
            for (int f = 0; f < 4; f++) acc[mi][ni][f] = 0.f;

    auto copy_tile = [&](int kt, int s) {
        int kcol = kt * 16;
#pragma unroll
        for (int q = 0; q < 2; q++) {
            int id = tid * 2 + q;
            int ar = id >> 2, seg = id & 3;
            const float* srcA = (kcol < K1)
                ? A  + (size_t)(row0 + ar) * K1 + kcol + seg * 4
                : A2 + (size_t)(row0 + ar) * K2 + (kcol - K1) + seg * 4;
            CP_ASYNC16(smem_u32(&As[s][ar][seg * 4]), srcA);
            int kr = id >> 5, bc = (id & 31) * 4;
            CP_ASYNC16(smem_u32(&Bs[s][kr][bc]),
                       Wl + (size_t)(kcol + kr) * Nl + col0 + bc);
        }
        CP_COMMIT;
    };

    int nk = (K1 + K2) >> 4;
    copy_tile(0, 0);
    for (int it = 0; it < nk; ++it) {
        CP_WAIT0;
        __syncthreads();
        if (it + 1 < nk) copy_tile(it + 1, (it + 1) & 1);
        int p = it & 1;
#pragma unroll
        for (int kk = 0; kk < 16; kk += 8) {
            uint32_t bH[4][2], bL[4][2];
#pragma unroll
            for (int ni = 0; ni < 4; ni++) {
                int n0 = wn * 32 + ni * 8 + gid;
                tfsplit(Bs[p][kk + tg][n0],     bH[ni][0], bL[ni][0]);
                tfsplit(Bs[p][kk + tg + 4][n0], bH[ni][1], bL[ni][1]);
            }
#pragma unroll
            for (int mi = 0; mi < 4; mi++) {
                int r0 = wm * 64 + mi * 16 + gid;
                uint32_t aH[4], aL[4];
                tfsplit(As[p][r0][kk + tg],         aH[0], aL[0]);
                tfsplit(As[p][r0 + 8][kk + tg],     aH[1], aL[1]);
                tfsplit(As[p][r0][kk + tg + 4],     aH[2], aL[2]);
                tfsplit(As[p][r0 + 8][kk + tg + 4], aH[3], aL[3]);
#pragma unroll
                for (int ni = 0; ni < 4; ni++) {
                    mma_tf32(acc[mi][ni], aH, bL[ni]);
                    mma_tf32(acc[mi][ni], aL, bH[ni]);
                    mma_tf32(acc[mi][ni], aH, bH[ni]);
                }
            }
        }
    }
#pragma unroll
    for (int mi = 0; mi < 4; mi++)
#pragma unroll
        for (int ni = 0; ni < 4; ni++) {
            int r = row0 + wm * 64 + mi * 16 + gid;
            int c = col0 + wn * 32 + ni * 8 + tg * 2;
#pragma unroll
            for (int h = 0; h < 2; h++) {
                int rr = r + h * 8;
                float o0 = acc[mi][ni][h * 2 + 0];
                float o1 = acc[mi][ni][h * 2 + 1];
                if (biasl) { o0 += biasl[c]; o1 += biasl[c + 1]; }
                float* cp = Cl + (size_t)rr * Nl + c;
                if (accum) { o0 += cp[0]; o1 += cp[1]; }
                if (act == 1) { o0 = gelu_f(o0); o1 = gelu_f(o1); }
                *(float2*)cp = make_float2(o0, o1);
            }
        }
}

// register sliding-window circular conv (sign=1) / corr (sign=0); 4 rows/block
// bmode: 0 = B shared; 1 = B row = gr&1023; 2 = B row = gr
__global__ __launch_bounds__(256)
void circ2_kernel(const float* __restrict__ A, const float* __restrict__ Bsrc,
                  float* __restrict__ out, int bmode, int sign)
{
    __shared__ float ad[4][1024];
    __shared__ float bvs[4][512];
    int tid = threadIdx.x;
    int lr = tid >> 6, lt = tid & 63;
    int gr = blockIdx.x * 4 + lr;
    const float* Arow = A + (size_t)gr * 512;
    const float* Brow = (bmode == 0) ? Bsrc
                      : (bmode == 1) ? (Bsrc + (size_t)(gr & 1023) * 512)
                                     : (Bsrc + (size_t)gr * 512);
    for (int i = lt; i < 1024; i += 64) ad[lr][i] = Arow[i & 511];
    for (int i = lt; i < 512; i += 64)  bvs[lr][i] = Brow[i];
    __syncthreads();

    int d0 = lt * 8;
    float accv[8];
#pragma unroll
    for (int i = 0; i < 8; i++) accv[i] = 0.f;
    float win[16];
    const float* adr = ad[lr];
    const float* bvr = bvs[lr];

    if (sign) {
        int base = 512 + d0 - 8;
        float4 p0 = *(const float4*)(adr + base + 8);
        float4 p1 = *(const float4*)(adr + base + 12);
        win[8] = p0.x; win[9] = p0.y; win[10] = p0.z; win[11] = p0.w;
        win[12] = p1.x; win[13] = p1.y; win[14] = p1.z; win[15] = p1.w;
        for (int m0 = 0; m0 < 512; m0 += 8) {
            float4 w0 = *(const float4*)(adr + base);
            float4 w1 = *(const float4*)(adr + base + 4);
            win[0] = w0.x; win[1] = w0.y; win[2] = w0.z; win[3] = w0.w;
            win[4] = w1.x; win[5] = w1.y; win[6] = w1.z; win[7] = w1.w;
            float4 b0 = *(const float4*)(bvr + m0);
            float4 b1 = *(const float4*)(bvr + m0 + 4);
            float bb[8] = {b0.x, b0.y, b0.z, b0.w, b1.x, b1.y, b1.z, b1.w};
#pragma unroll
            for (int mm = 0; mm < 8; mm++)
#pragma unroll
                for (int i = 0; i < 8; i++)
                    accv[i] += bb[mm] * win[8 + i - mm];
#pragma unroll
            for (int k = 0; k < 8; k++) win[8 + k] = win[k];
            base -= 8;
        }
    } else {
        int base = 512 - d0 - 8;
        float4 p0 = *(const float4*)(adr + base);
        float4 p1 = *(const float4*)(adr + base + 4);
        win[0] = p0.x; win[1] = p0.y; win[2] = p0.z; win[3] = p0.w;
        win[4] = p1.x; win[5] = p1.y; win[6] = p1.z; win[7] = p1.w;
        for (int m0 = 0; m0 < 512; m0 += 8) {
            float4 w0 = *(const float4*)(adr + base + 8);
            float4 w1 = *(const float4*)(adr + base + 12);
            win[8] = w0.x; win[9] = w0.y; win[10] = w0.z; win[11] = w0.w;
            win[12] = w1.x; win[13] = w1.y; win[14] = w1.z; win[15] = w1.w;
            float4 b0 = *(const float4*)(bvr + m0);
            float4 b1 = *(const float4*)(bvr + m0 + 4);
            float bb[8] = {b0.x, b0.y, b0.z, b0.w, b1.x, b1.y, b1.z, b1.w};
#pragma unroll
            for (int mm = 0; mm < 8; mm++)
#pragma unroll
                for (int i = 0; i < 8; i++)
                    accv[i] += bb[mm] * win[8 + mm - i];
#pragma unroll
            for (int k = 0; k < 8; k++) win[k] = win[k + 8];
            base += 8;
        }
    }
    *(float4*)(out + (size_t)gr * 512 + d0) = make_float4(accv[0], accv[1], accv[2], accv[3]);
    *(float4*)(out + (size_t)gr * 512 + d0 + 4) = make_float4(accv[4], accv[5], accv[6], accv[7]);
}

__global__ __launch_bounds__(128)
void rownorm_kernel(float* __restrict__ keys)
{
    int row = blockIdx.x, tid = threadIdx.x;
    __shared__ float rs[4];
    float4 v = *(float4*)(keys + (size_t)row * 512 + tid * 4);
    float ss = v.x*v.x + v.y*v.y + v.z*v.z + v.w*v.w;
#pragma unroll
    for (int off = 16; off; off >>= 1) ss += __shfl_xor_sync(0xffffffffu, ss, off);
    int w = tid >> 5, l = tid & 31;
    if (l == 0) rs[w] = ss;
    __syncthreads();
    ss = rs[0] + rs[1] + rs[2] + rs[3];
    float inv = 1.f / fmaxf(sqrtf(ss), 1e-12f);
    v.x *= inv; v.y *= inv; v.z *= inv; v.w *= inv;
    *(float4*)(keys + (size_t)row * 512 + tid * 4) = v;
}

// ---- phase 2 FUSED (512 threads): blocks 0-7 scan (2 barriers/step, reg hcm,
//      all-warp post-B2 softmax); blocks 8..519 Wo gemm tiles ----
__global__ __launch_bounds__(512)
void phase2_fused(const float* __restrict__ v_g, const float* __restrict__ bound_g,
                  const float* __restrict__ preg1_g, const float* __restrict__ Wg1,
                  const float* __restrict__ Wg2, const float* __restrict__ bg2,
                  const float* __restrict__ bsa, float* __restrict__ mixed_g,
                  float* __restrict__ hcm_out,
                  const float* __restrict__ Qm, const float* __restrict__ Wo,
                  const float* __restrict__ bo, float* __restrict__ preo)
{
    __shared__ __align__(16) char sbuf[45312];
    int tid = threadIdx.x;
    int lane = tid & 31, wid = tid >> 5;

    if (blockIdx.x >= 8) {
        float (*As)[128][20] = (float (*)[128][20])sbuf;
        float (*Bs)[16][136] = (float (*)[16][136])(sbuf + 20480);
        int t = blockIdx.x - 8;
        int col0 = (t & 7) * 128, row0 = (t >> 3) * 128;
        int wm = wid & 3, wn = wid >> 2;
        int gid = lane >> 2, tg = lane & 3;
        const int K = H_, Nn = H_;

        float acc[2][4][4];
#pragma unroll
        for (int mi = 0; mi < 2; mi++)
#pragma unroll
            for (int ni = 0; ni < 4; ni++)
#pragma unroll
                for (int f = 0; f < 4; f++) acc[mi][ni][f] = 0.f;

        auto copy_tile = [&](int kt, int s) {
            int ar = tid >> 2, seg = tid & 3;
            CP_ASYNC16(smem_u32(&As[s][ar][seg * 4]),
                       Qm + (size_t)(row0 + ar) * K + kt * 16 + seg * 4);
            int kr = tid >> 5, bc = (tid & 31) * 4;
            CP_ASYNC16(smem_u32(&Bs[s][kr][bc]),
                       Wo + (size_t)(kt * 16 + kr) * Nn + col0 + bc);
            CP_COMMIT;
        };

        int nk = K >> 4;
        copy_tile(0, 0);
        for (int it = 0; it < nk; ++it) {
            CP_WAIT0;
            __syncthreads();
            if (it + 1 < nk) copy_tile(it + 1, (it + 1) & 1);
            int p = it & 1;
#pragma unroll
            for (int kk = 0; kk < 16; kk += 8) {
                uint32_t bH[4][2], bL[4][2];
#pragma unroll
                for (int ni = 0; ni < 4; ni++) {
                    int n0 = wn * 32 + ni * 8 + gid;
                    tfsplit(Bs[p][kk + tg][n0],     bH[ni][0], bL[ni][0]);
                    tfsplit(Bs[p][kk + tg + 4][n0], bH[ni][1], bL[ni][1]);
                }
#pragma unroll
                for (int mi = 0; mi < 2; mi++) {
                    int r0 = wm * 32 + mi * 16 + gid;
                    uint32_t aH[4], aL[4];
                    tfsplit(As[p][r0][kk + tg],         aH[0], aL[0]);
                    tfsplit(As[p][r0 + 8][kk + tg],     aH[1], aL[1]);
                    tfsplit(As[p][r0][kk + tg + 4],     aH[2], aL[2]);
                    tfsplit(As[p][r0 + 8][kk + tg + 4], aH[3], aL[3]);
#pragma unroll
                    for (int ni = 0; ni < 4; ni++) {
                        mma_tf32(acc[mi][ni], aH, bL[ni]);
                        mma_tf32(acc[mi][ni], aL, bH[ni]);
                        mma_tf32(acc[mi][ni], aH, bH[ni]);
                    }
                }
            }
        }
#pragma unroll
        for (int mi = 0; mi < 2; mi++)
#pragma unroll
            for (int ni = 0; ni < 4; ni++) {
                int r = row0 + wm * 32 + mi * 16 + gid;
                int c = col0 + wn * 32 + ni * 8 + tg * 2;
#pragma unroll
                for (int h = 0; h < 2; h++) {
                    int rr = r + h * 8;
                    float o0 = acc[mi][ni][h * 2 + 0] + bo[c];
                    float o1 = acc[mi][ni][h * 2 + 1] + bo[c + 1];
                    *(float2*)(preo + (size_t)rr * Nn + c) = make_float2(o0, o1);
                }
            }
        return;
    }

    // ---------- scan path (512 threads, 2 barriers/step) ----------
    float* hcm_s   = (float*)sbuf;                 // 8192 f (mirror)
    float* g_s     = hcm_s + 8192;                 // 1024 f
    float* v_s     = g_s + 1024;                   // 2*512
    float* bnd_s   = v_s + 1024;                   // 2*512
    float* scores_s= bnd_s + 1024;                 // 16
    float* stats_s = scores_s + 16;

    int b = blockIdx.x;
    int w = wid, l = lane;

    float wg1a[16], wg1b[16], wg2r[32], hr[16];
#pragma unroll
    for (int n = 0; n < 16; ++n) {
        wg1a[n] = Wg1[(size_t)(1536 + n) * 1024 + tid];
        wg1b[n] = Wg1[(size_t)(1536 + n) * 1024 + tid + 512];
        hr[n] = 0.f;
    }
#pragma unroll
    for (int i = 0; i < 32; ++i)
        wg2r[i] = Wg2[(size_t)(l + 32 * i) * 16 + w];
    float bg2w = bg2[w];
    float bsa0 = bsa[0];

    for (int i = tid; i < 8192; i += 512) hcm_s[i] = 0.f;

    size_t rbase = (size_t)b * S_;
    v_s[tid]   = v_g[rbase * 512 + tid];
    bnd_s[tid] = bound_g[rbase * 512 + tid];
    float pg0 = preg1_g[rbase * 1024 + tid];
    float pg1 = preg1_g[rbase * 1024 + tid + 512];
    float Av = v_g[(rbase + 1) * 512 + tid];
    float Ab = bound_g[(rbase + 1) * 512 + tid];
    float Ap0 = preg1_g[(rbase + 1) * 1024 + tid];
    float Ap1 = preg1_g[(rbase + 1) * 1024 + tid + 512];
    float Bv = v_g[(rbase + 2) * 512 + tid];
    float Bb = bound_g[(rbase + 2) * 512 + tid];
    float Bp0 = preg1_g[(rbase + 2) * 1024 + tid];
    float Bp1 = preg1_g[(rbase + 2) * 1024 + tid + 512];
    __syncthreads();

    for (int t = 0; t < S_; ++t) {
        int cur = t & 1;
        // segA: scores+stats from REGISTER hcm (own slot)
        float dv = 0.f, dh = 0.f;
#pragma unroll
        for (int i = 0; i < 16; ++i) {
            dv += hr[i] * v_s[cur * 512 + l + i * 32];
            dh += hr[i] * hr[i];
        }
#pragma unroll
        for (int off = 16; off; off >>= 1) {
            dv += __shfl_xor_sync(0xffffffffu, dv, off);
            dh += __shfl_xor_sync(0xffffffffu, dh, off);
        }
        if (l == 0) { scores_s[w] = dv + bsa0; stats_s[w] = sqrtf(dh); }
        __syncthreads();                                  // B1
        // segB: snapshot mirror first (LDS latency hides under gating math)
        float hm[16];
#pragma unroll
        for (int n = 0; n < 16; ++n) hm[n] = hcm_s[n * 512 + tid];
        float scr = (l < 16) ? scores_s[l] : -3.4e38f;
        {
            float a0 = pg0, a1 = pg1;
#pragma unroll
            for (int n = 0; n < 16; ++n) {
                float st = stats_s[n];
                a0 += st * wg1a[n];
                a1 += st * wg1b[n];
            }
            g_s[tid] = gelu_f(a0);
            g_s[tid + 512] = gelu_f(a1);
        }
        v_s[(cur ^ 1) * 512 + tid] = Av;
        bnd_s[(cur ^ 1) * 512 + tid] = Ab;
        __syncthreads();                                  // B2
        // segC: gates (warp-private), all-warp softmax, mixed, update
        float ga = 0.f;
#pragma unroll
        for (int i = 0; i < 32; ++i)
            ga += g_s[l + i * 32] * wg2r[i];
#pragma unroll
        for (int off = 16; off; off >>= 1)
            ga += __shfl_xor_sync(0xffffffffu, ga, off);
        float gw = 1.f / (1.f + __expf(-(ga + bg2w)));
        float mxv = scr;
#pragma unroll
        for (int off = 8; off; off >>= 1)
            mxv = fmaxf(mxv, __shfl_xor_sync(0xffffffffu, mxv, off));
        float e = (l < 16) ? __expf(scr - mxv) : 0.f;
        float su = e;
#pragma unroll
        for (int off = 8; off; off >>= 1)
            su += __shfl_xor_sync(0xffffffffu, su, off);
        float myw = e * __frcp_rn(su);
        float mx = 0.f;
#pragma unroll
        for (int n = 0; n < 16; ++n)
            mx += __shfl_sync(0xffffffffu, myw, n) * hm[n];
        mixed_g[(rbase + t) * 512 + tid] = mx;
#pragma unroll
        for (int i = 0; i < 16; ++i) {
            int d = l + 32 * i;
            hr[i] = DECAYF * hr[i] + gw * bnd_s[cur * 512 + d];
            hcm_s[w * 512 + d] = hr[i];
        }
        pg0 = Ap0; pg1 = Ap1;
        Av = Bv; Ab = Bb; Ap0 = Bp0; Ap1 = Bp1;
        if (t + 3 < S_) {
            size_t rb = rbase + t + 3;
            Bv  = v_g[rb * 512 + tid];
            Bb  = bound_g[rb * 512 + tid];
            Bp0 = preg1_g[rb * 1024 + tid];
            Bp1 = preg1_g[rb * 1024 + tid + 512];
        }
    }
    __syncthreads();
    for (int i = tid; i < 8192; i += 512)
        hcm_out[(size_t)b * 8192 + i] = hcm_s[i];
}

__global__ __launch_bounds__(256)
void ln_kernel(const float* __restrict__ hs, const float* __restrict__ preo,
               const float* __restrict__ lng, const float* __restrict__ lnb,
               float* __restrict__ out)
{
    int row = blockIdx.x, tid = threadIdx.x;
    __shared__ float rs[8], rs2[8];
    size_t base = (size_t)row * 1024;
    float v[4]; float s = 0.f, s2 = 0.f;
#pragma unroll
    for (int i = 0; i < 4; i++) {
        int h = tid + i * 256;
        float x = hs[base + h] + preo[base + h];
        v[i] = x; s += x; s2 += x * x;
    }
#pragma unroll
    for (int off = 16; off; off >>= 1) {
        s  += __shfl_xor_sync(0xffffffffu, s, off);
        s2 += __shfl_xor_sync(0xffffffffu, s2, off);
    }
    int w = tid >> 5, l = tid & 31;
    if (l == 0) { rs[w] = s; rs2[w] = s2; }
    __syncthreads();
    s = 0.f; s2 = 0.f;
#pragma unroll
    for (int i = 0; i < 8; i++) { s += rs[i]; s2 += rs2[i]; }
    float mu = s * (1.f / 1024.f);
    float var = s2 * (1.f / 1024.f) - mu * mu;
    float rstd = rsqrtf(var + EPS_LN);
#pragma unroll
    for (int i = 0; i < 4; i++) {
        int h = tid + i * 256;
        out[base + h] = (v[i] - mu) * rstd * lng[h] + lnb[h];
    }
}

extern "C" void kernel_launch(void* const* d_in, const int* in_sizes, int n_in,
                              void* d_out, int out_size)
{
    const float* hs  = (const float*)d_in[0];
    const float* pos = (const float*)d_in[1];
    const float* Wi  = (const float*)d_in[2];
    const float* bi  = (const float*)d_in[3];
    const float* Wq  = (const float*)d_in[4];
    const float* bq  = (const float*)d_in[5];
    const float* Wk1 = (const float*)d_in[6];
    const float* bk1 = (const float*)d_in[7];
    const float* Wk2 = (const float*)d_in[8];
    const float* bk2 = (const float*)d_in[9];
    const float* Wsa = (const float*)d_in[10];
    const float* bsa = (const float*)d_in[11];
    const float* Wg1 = (const float*)d_in[12];
    const float* bg1 = (const float*)d_in[13];
    const float* Wg2 = (const float*)d_in[14];
    const float* bg2 = (const float*)d_in[15];
    const float* Wo  = (const float*)d_in[16];
    const float* bo  = (const float*)d_in[17];
    const float* lng = (const float*)d_in[18];
    const float* lnb = (const float*)d_in[19];
    float* out = (float*)d_out;

    float *items, *queries, *khid, *keys, *bound, *v, *preg1, *preo, *mixed, *ctx;
    cudaGetSymbolAddress((void**)&items,   g_items);
    cudaGetSymbolAddress((void**)&queries, g_queries);
    cudaGetSymbolAddress((void**)&khid,    g_khid);
    cudaGetSymbolAddress((void**)&keys,    g_keys);
    cudaGetSymbolAddress((void**)&bound,   g_bound);
    cudaGetSymbolAddress((void**)&v,       g_v);
    cudaGetSymbolAddress((void**)&preg1,   g_preg1);
    cudaGetSymbolAddress((void**)&preo,    g_preo);
    cudaGetSymbolAddress((void**)&mixed,   g_mixed);
    cudaGetSymbolAddress((void**)&ctx,     g_ctx);

    dim3 gN(H_ / 128, BS_ / 128);
    dim3 gD(D_ / 128, BS_ / 128);
    dim3 gF((H_ + D_) / 128, BS_ / 128);   // fused dual-W first GEMM

    // queries = hs@Wq + bq ; items = hs@Wi + bi  (single pass over hs)
    tgemm_kernel<<<gF, 256>>>(hs, H_, nullptr, 0, Wq, H_, Wi, D_,
                              bq, bi, queries, items, 0, 0);
    tgemm_kernel<<<gN, 256>>>(queries, H_, nullptr, 0, Wk1, H_, nullptr, 0,
                              bk1, nullptr, khid, nullptr, 1, 0);
    tgemm_kernel<<<gD, 256>>>(khid, H_, nullptr, 0, Wk2, D_, nullptr, 0,
                              bk2, nullptr, keys, nullptr, 0, 0);
    rownorm_kernel<<<BS_, 128>>>(keys);
    circ2_kernel<<<BS_ / 4, 256>>>(keys, Wsa, v, 0, 1);      // v = conv(keys, Wsa)
    circ2_kernel<<<BS_ / 4, 256>>>(items, pos, bound, 1, 1); // bound = conv(items, pos)
    // preg1 = [queries|items] @ Wg1[0:1536] + bg1
    tgemm_kernel<<<gN, 256>>>(queries, H_, items, D_, Wg1, H_, nullptr, 0,
                              bg1, nullptr, preg1, nullptr, 0, 0);

    phase2_fused<<<8 + 512, 512>>>(v, bound, preg1, Wg1, Wg2, bg2, bsa,
                                   mixed, out + (size_t)BS_ * H_,
                                   queries, Wo, bo, preo);

    circ2_kernel<<<BS_ / 4, 256>>>(keys, mixed, ctx, 2, 0);  // ctx = corr(mixed, keys)
    tgemm_kernel<<<gN, 256>>>(ctx, D_, nullptr, 0, Wo + (size_t)H_ * H_, H_, nullptr, 0,
                              nullptr, nullptr, preo, nullptr, 0, 1);
    ln_kernel<<<BS_, 256>>>(hs, preo, lng, lnb, out);
}